// round 6
// baseline (speedup 1.0000x reference)
#include <cuda_runtime.h>
#include <cstdint>

#define D 512
#define NL1 64
#define NL2 512
#define NL3 2048
#define BATCH 16
#define SEQ 512

// ---------------- device scratch (static, no allocs) ----------------
__device__ float g_E   [2624 * D];     // [emb0; emb1; emb2], tf32-rounded
__device__ float g_Q   [2624 * D];
__device__ float g_KV0 [576  * 1024];
__device__ float g_KV1 [2624 * 1024];
__device__ float g_KV2 [2560 * 1024];
__device__ float g_OPRE[2624 * D];     // tf32-rounded at write
__device__ float g_OPRJ[2624 * D];
__device__ float g_AGG [2624 * D];
__device__ float g_R   [2624 * D];
__device__ float g_ADP0[64 * 64];
__device__ int   g_P1  [NL2];
__device__ int   g_P2  [NL3];
__device__ float g_ATT [(size_t)BATCH * NL3 * SEQ];   // rounded probs after softmax
__device__ float g_INPR[(size_t)BATCH * SEQ * D];     // rounded inputs
__device__ float g_INW [3 * 3 * D * D];               // rounded in_w
__device__ float g_OUTW[3 * D * D];                   // rounded out_w
__device__ float g_FEATR[NL3 * D];                    // rounded features

__device__ __forceinline__ uint32_t f2tf32(float x) {
    uint32_t t;
    asm("cvt.rna.tf32.f32 %0, %1;" : "=r"(t) : "f"(x));
    return t;
}

// ---------------- tf32 rounding pass (n multiple of 4) ----------------
__global__ void round_tf32_kernel(const float* __restrict__ src, float* __restrict__ dst,
                                  long n4) {
    long i = (blockIdx.x * (long)blockDim.x + threadIdx.x);
    if (i < n4) {
        float4 v = reinterpret_cast<const float4*>(src)[i];
        v.x = __uint_as_float(f2tf32(v.x));
        v.y = __uint_as_float(f2tf32(v.y));
        v.z = __uint_as_float(f2tf32(v.z));
        v.w = __uint_as_float(f2tf32(v.w));
        reinterpret_cast<float4*>(dst)[i] = v;
    }
}

// ---------------- parent extraction ----------------
__global__ void extract_parents(const float* __restrict__ H0,
                                const float* __restrict__ H1,
                                int* __restrict__ p1, int* __restrict__ p2) {
    int t = blockIdx.x * blockDim.x + threadIdx.x;
    if (t < NL2) {
        int par = 0;
        for (int i = 0; i < NL1; i++)
            if (H0[(long)i * NL2 + t] > 0.5f) par = i;
        p1[t] = par;
    } else if (t < NL2 + NL3) {
        int j = t - NL2;
        int par = 0;
        for (int i = 0; i < NL2; i++)
            if (H1[(long)i * NL3 + j] > 0.5f) par = i;
        p2[j] = par;
    }
}

// ---------------- tf32 tensor-core GEMM, cp.async double-buffered ----------------
// Operands are already tf32-rounded; fragment load is a raw bit load.
#define AST 20   // [row][k] smem stride (floats)
#define BST 136  // [k][n] smem stride for NN-B

__device__ __forceinline__ void cpa16(uint32_t dst, const float* src, bool pred) {
    int sz = pred ? 16 : 0;
    asm volatile("cp.async.ca.shared.global [%0], [%1], 16, %2;\n"
                 :: "r"(dst), "l"(src), "r"(sz));
}

template <bool TRANSB>
__global__ __launch_bounds__(256, 2)
void tgemm_kernel(const float* __restrict__ Ag, const float* __restrict__ Bg,
                  const float* __restrict__ bias, float* __restrict__ Cg,
                  int M, int N, int K, long sA, long sB, long sC) {
    __shared__ float As[2][128 * AST];
    __shared__ float Bs[2][TRANSB ? 128 * AST : 16 * BST];

    const float* A = Ag + (long)blockIdx.z * sA;
    const float* B = Bg + (long)blockIdx.z * sB;
    float*       C = Cg + (long)blockIdx.z * sC;

    const int bm = blockIdx.y * 128;
    const int bn = blockIdx.x * 128;
    const int tid = threadIdx.x;
    const int w = tid >> 5, lane = tid & 31;
    const int wm = (w & 1) * 64;
    const int wn = (w >> 1) * 32;
    const int lq = lane >> 2;
    const int lr = lane & 3;

    const int ar0 = tid >> 2,          ak0 = (tid & 3) << 2;
    const int ar1 = (tid + 256) >> 2,  ak1 = ((tid + 256) & 3) << 2;
    const int bk0 = tid >> 5,          bq0 = (tid & 31) << 2;
    const int bk1 = (tid + 256) >> 5,  bq1 = ((tid + 256) & 31) << 2;

    const uint32_t asm0 = (uint32_t)__cvta_generic_to_shared(&As[0][0]);
    const uint32_t asm1 = (uint32_t)__cvta_generic_to_shared(&As[1][0]);
    const uint32_t bsm0 = (uint32_t)__cvta_generic_to_shared(&Bs[0][0]);
    const uint32_t bsm1 = (uint32_t)__cvta_generic_to_shared(&Bs[1][0]);

    float c[4][4][4];
#pragma unroll
    for (int mi = 0; mi < 4; mi++)
#pragma unroll
        for (int ni = 0; ni < 4; ni++)
#pragma unroll
            for (int r = 0; r < 4; r++) c[mi][ni][r] = 0.f;

    const int T = K >> 4;

    {
        cpa16(asm0 + (ar0 * AST + ak0) * 4, A + (long)(bm + ar0) * K + ak0, bm + ar0 < M);
        cpa16(asm0 + (ar1 * AST + ak1) * 4, A + (long)(bm + ar1) * K + ak1, bm + ar1 < M);
        if (TRANSB) {
            cpa16(bsm0 + (ar0 * AST + ak0) * 4, B + (long)(bn + ar0) * K + ak0, bn + ar0 < N);
            cpa16(bsm0 + (ar1 * AST + ak1) * 4, B + (long)(bn + ar1) * K + ak1, bn + ar1 < N);
        } else {
            cpa16(bsm0 + (bk0 * BST + bq0) * 4, B + (long)bk0 * N + bn + bq0, bn + bq0 < N);
            cpa16(bsm0 + (bk1 * BST + bq1) * 4, B + (long)bk1 * N + bn + bq1, bn + bq1 < N);
        }
        asm volatile("cp.async.commit_group;\n" ::);
    }

    for (int t = 0; t < T; t++) {
        const int cur = t & 1;
        asm volatile("cp.async.wait_group 0;\n" ::);
        __syncthreads();

        if (t + 1 < T) {
            const int k1 = (t + 1) << 4;
            const uint32_t an = cur ? asm0 : asm1;
            const uint32_t bn_s = cur ? bsm0 : bsm1;
            cpa16(an + (ar0 * AST + ak0) * 4, A + (long)(bm + ar0) * K + k1 + ak0, bm + ar0 < M);
            cpa16(an + (ar1 * AST + ak1) * 4, A + (long)(bm + ar1) * K + k1 + ak1, bm + ar1 < M);
            if (TRANSB) {
                cpa16(bn_s + (ar0 * AST + ak0) * 4, B + (long)(bn + ar0) * K + k1 + ak0, bn + ar0 < N);
                cpa16(bn_s + (ar1 * AST + ak1) * 4, B + (long)(bn + ar1) * K + k1 + ak1, bn + ar1 < N);
            } else {
                cpa16(bn_s + (bk0 * BST + bq0) * 4, B + (long)(k1 + bk0) * N + bn + bq0, bn + bq0 < N);
                cpa16(bn_s + (bk1 * BST + bq1) * 4, B + (long)(k1 + bk1) * N + bn + bq1, bn + bq1 < N);
            }
            asm volatile("cp.async.commit_group;\n" ::);
        }

        {
            const float* as = As[cur];
            const float* bs = Bs[cur];
#pragma unroll
            for (int ks = 0; ks < 16; ks += 8) {
                uint32_t a[4][4], b[4][2];
#pragma unroll
                for (int mi = 0; mi < 4; mi++) {
                    int m = wm + mi * 16;
                    a[mi][0] = __float_as_uint(as[(m + lq) * AST + ks + lr]);
                    a[mi][1] = __float_as_uint(as[(m + 8 + lq) * AST + ks + lr]);
                    a[mi][2] = __float_as_uint(as[(m + lq) * AST + ks + 4 + lr]);
                    a[mi][3] = __float_as_uint(as[(m + 8 + lq) * AST + ks + 4 + lr]);
                }
#pragma unroll
                for (int ni = 0; ni < 4; ni++) {
                    int n = wn + ni * 8;
                    if (TRANSB) {
                        b[ni][0] = __float_as_uint(bs[(n + lq) * AST + ks + lr]);
                        b[ni][1] = __float_as_uint(bs[(n + lq) * AST + ks + 4 + lr]);
                    } else {
                        b[ni][0] = __float_as_uint(bs[(ks + lr) * BST + n + lq]);
                        b[ni][1] = __float_as_uint(bs[(ks + 4 + lr) * BST + n + lq]);
                    }
                }
#pragma unroll
                for (int mi = 0; mi < 4; mi++)
#pragma unroll
                    for (int ni = 0; ni < 4; ni++)
                        asm volatile(
                            "mma.sync.aligned.m16n8k8.row.col.f32.tf32.tf32.f32 "
                            "{%0,%1,%2,%3}, {%4,%5,%6,%7}, {%8,%9}, {%0,%1,%2,%3};"
                            : "+f"(c[mi][ni][0]), "+f"(c[mi][ni][1]),
                              "+f"(c[mi][ni][2]), "+f"(c[mi][ni][3])
                            : "r"(a[mi][0]), "r"(a[mi][1]), "r"(a[mi][2]), "r"(a[mi][3]),
                              "r"(b[ni][0]), "r"(b[ni][1]));
            }
        }
    }

#pragma unroll
    for (int mi = 0; mi < 4; mi++) {
#pragma unroll
        for (int ni = 0; ni < 4; ni++) {
            int row0 = bm + wm + mi * 16 + lq;
            int col = bn + wn + ni * 8 + lr * 2;
            if (col >= N) continue;
            float b0 = 0.f, b1 = 0.f;
            if (bias) { b0 = bias[col]; b1 = bias[col + 1]; }
            if (row0 < M) {
                C[(long)row0 * N + col] = c[mi][ni][0] + b0;
                C[(long)row0 * N + col + 1] = c[mi][ni][1] + b1;
            }
            if (row0 + 8 < M) {
                C[(long)(row0 + 8) * N + col] = c[mi][ni][2] + b0;
                C[(long)(row0 + 8) * N + col + 1] = c[mi][ni][3] + b1;
            }
        }
    }
}

// ---------------- row softmax (in place, writes tf32-rounded probs) ----------------
__global__ void row_softmax(float* __restrict__ data, int cols) {
    long row = blockIdx.x;
    float* p = data + row * (long)cols;
    __shared__ float red[33];
    int tid = threadIdx.x, lane = tid & 31, w = tid >> 5;
    int nw = blockDim.x >> 5;

    float m = -3.4e38f;
    for (int c = tid; c < cols; c += blockDim.x) m = fmaxf(m, p[c]);
    for (int o = 16; o; o >>= 1) m = fmaxf(m, __shfl_xor_sync(0xffffffffu, m, o));
    if (lane == 0) red[w] = m;
    __syncthreads();
    if (tid == 0) {
        float mm = red[0];
        for (int i = 1; i < nw; i++) mm = fmaxf(mm, red[i]);
        red[32] = mm;
    }
    __syncthreads();
    m = red[32];
    __syncthreads();

    float sum = 0.f;
    for (int c = tid; c < cols; c += blockDim.x) {
        float e = __expf(p[c] - m);
        p[c] = e;
        sum += e;
    }
    for (int o = 16; o; o >>= 1) sum += __shfl_xor_sync(0xffffffffu, sum, o);
    if (lane == 0) red[w] = sum;
    __syncthreads();
    if (tid == 0) {
        float s = 0.f;
        for (int i = 0; i < nw; i++) s += red[i];
        red[32] = s;
    }
    __syncthreads();
    float inv = 1.f / red[32];
    for (int c = tid; c < cols; c += blockDim.x)
        p[c] = __uint_as_float(f2tf32(p[c] * inv));
}

// ---------------- sibling-group masked self-attention agg ----------------
#define MAXG 64
__global__ __launch_bounds__(256)
void group_agg(const float* __restrict__ h, const int* __restrict__ parent,
               int nNodes, float* __restrict__ agg) {
    __shared__ int cnt;
    __shared__ int idx[MAXG];
    __shared__ float lg[MAXG][MAXG + 1];
    int g = blockIdx.x;
    if (threadIdx.x == 0) cnt = 0;
    __syncthreads();
    for (int j = threadIdx.x; j < nNodes; j += blockDim.x)
        if (parent[j] == g) {
            int s = atomicAdd(&cnt, 1);
            if (s < MAXG) idx[s] = j;
        }
    __syncthreads();
    int n = cnt;
    if (n > MAXG) n = MAXG;
    if (n == 0) return;

    int lane = threadIdx.x & 31, warp = threadIdx.x >> 5, nw = blockDim.x >> 5;

    for (int p = warp; p < n * n; p += nw) {
        int a = p / n, b = p % n;
        const float* ha = h + (long)idx[a] * D;
        const float* hb = h + (long)idx[b] * D;
        float s = 0.f;
        for (int d = lane * 4; d < D; d += 128) {
            float4 x = *reinterpret_cast<const float4*>(ha + d);
            float4 y = *reinterpret_cast<const float4*>(hb + d);
            s += x.x * y.x + x.y * y.y + x.z * y.z + x.w * y.w;
        }
        for (int o = 16; o; o >>= 1) s += __shfl_xor_sync(0xffffffffu, s, o);
        if (lane == 0) lg[a][b] = s;
    }
    __syncthreads();

    for (int a = warp; a < n; a += nw) {
        float m = -3.4e38f;
        for (int j = lane; j < n; j += 32) m = fmaxf(m, lg[a][j]);
        for (int o = 16; o; o >>= 1) m = fmaxf(m, __shfl_xor_sync(0xffffffffu, m, o));
        float s = 0.f;
        for (int j = lane; j < n; j += 32) {
            float e = __expf(lg[a][j] - m);
            lg[a][j] = e;
            s += e;
        }
        for (int o = 16; o; o >>= 1) s += __shfl_xor_sync(0xffffffffu, s, o);
        float inv = 1.f / s;
        for (int j = lane; j < n; j += 32) lg[a][j] *= inv;
    }
    __syncthreads();

    for (int a = 0; a < n; a++) {
        long orow = (long)idx[a] * D;
        for (int d = threadIdx.x; d < D; d += blockDim.x) {
            float acc = 0.f;
            for (int b = 0; b < n; b++) acc += lg[a][b] * h[(long)idx[b] * D + d];
            agg[orow + d] = acc;
        }
    }
}

// ---------------- sparse hierarchy MHA over fused KV (ld = 1024) ----------------
// Output rounded to tf32 (feeds the OPRJ GEMM).
#define MAXKEY 96
__global__ __launch_bounds__(256)
void sparse_mha(const float* __restrict__ q, const float* __restrict__ kv,
                float* __restrict__ o,
                const int* __restrict__ parentArr, int selfOff,
                const int* __restrict__ childParent, int nChild, int childOff) {
    int i = blockIdx.x;
    __shared__ int cnt;
    __shared__ int keys[MAXKEY];
    __shared__ float sc[8][MAXKEY];
    if (threadIdx.x == 0) {
        int c = 0;
        keys[c++] = selfOff + i;
        if (parentArr) keys[c++] = parentArr[i];
        cnt = c;
    }
    __syncthreads();
    for (int j = threadIdx.x; j < nChild; j += blockDim.x)
        if (childParent[j] == i) {
            int s = atomicAdd(&cnt, 1);
            if (s < MAXKEY) keys[s] = childOff + j;
        }
    __syncthreads();
    int n = cnt;
    if (n > MAXKEY) n = MAXKEY;

    int lane = threadIdx.x & 31;
    int h = threadIdx.x >> 5;
    const float* qrow = q + (long)i * D + h * 64;
    float ql0 = qrow[lane], ql1 = qrow[lane + 32];

    for (int s = 0; s < n; s++) {
        const float* kp = kv + (long)keys[s] * 1024 + h * 64;
        float pa = ql0 * kp[lane] + ql1 * kp[lane + 32];
        for (int off = 16; off; off >>= 1) pa += __shfl_xor_sync(0xffffffffu, pa, off);
        if (lane == 0) sc[h][s] = pa * 0.125f;
    }
    __syncwarp();
    float m = -3.4e38f;
    for (int s = lane; s < n; s += 32) m = fmaxf(m, sc[h][s]);
    for (int off = 16; off; off >>= 1) m = fmaxf(m, __shfl_xor_sync(0xffffffffu, m, off));
    float sum = 0.f;
    for (int s = lane; s < n; s += 32) {
        float e = __expf(sc[h][s] - m);
        sc[h][s] = e;
        sum += e;
    }
    for (int off = 16; off; off >>= 1) sum += __shfl_xor_sync(0xffffffffu, sum, off);
    float inv = 1.f / sum;
    __syncwarp();

    float a0 = 0.f, a1 = 0.f;
    for (int s = 0; s < n; s++) {
        float w = sc[h][s] * inv;
        const float* vp = kv + (long)keys[s] * 1024 + 512 + h * 64;
        a0 += w * vp[lane];
        a1 += w * vp[lane + 32];
    }
    float* orow = o + (long)i * D + h * 64;
    orow[lane] = __uint_as_float(f2tf32(a0));
    orow[lane + 32] = __uint_as_float(f2tf32(a1));
}

// ---------------- stack/combine ----------------
__global__ void combine_kernel(const float* __restrict__ a, const float* __restrict__ h,
                               const float* __restrict__ o, const float* __restrict__ sw,
                               float* __restrict__ r, long n) {
    long i = blockIdx.x * (long)blockDim.x + threadIdx.x;
    if (i < n) r[i] = sw[0] * a[i] + sw[1] * h[i] + sw[2] * o[i];
}

// ---------------- features: exact to out, rounded copy for ATT GEMM ----------------
__global__ void features_kernel(const float* __restrict__ r, const int* __restrict__ p1,
                                const int* __restrict__ p2, const float* __restrict__ fw,
                                float* __restrict__ out, float* __restrict__ outR) {
    int f = blockIdx.x;
    int d = threadIdx.x;  // blockDim = 512
    int pp = p2[f];
    int gp = p1[pp];
    const float* r0 = r;
    const float* r1 = r + 64 * D;
    const float* r2 = r + 576 * D;
    float v = fw[0] * r0[(long)gp * D + d] + fw[1] * r1[(long)pp * D + d]
            + fw[2] * r2[(long)f * D + d];
    out[(long)f * D + d] = v;
    outR[(long)f * D + d] = __uint_as_float(f2tf32(v));
}

// ---------------- host ----------------
#define SYM(p, s)                                    \
    do {                                             \
        void* _t = nullptr;                          \
        cudaGetSymbolAddress(&_t, s);                \
        p = (decltype(p))_t;                         \
    } while (0)

static void launch_nt(float* C, const float* A, const float* B, const float* bias,
                      int M, int N, int K, long sA, long sB, long sC, int bz) {
    dim3 grid((N + 127) / 128, (M + 127) / 128, bz);
    tgemm_kernel<true><<<grid, 256>>>(A, B, bias, C, M, N, K, sA, sB, sC);
}
static void launch_nn(float* C, const float* A, const float* B, const float* bias,
                      int M, int N, int K, long sA, long sB, long sC, int bz) {
    dim3 grid((N + 127) / 128, (M + 127) / 128, bz);
    tgemm_kernel<false><<<grid, 256>>>(A, B, bias, C, M, N, K, sA, sB, sC);
}
static void launch_round(const float* src, float* dst, long n) {
    long n4 = n >> 2;
    round_tf32_kernel<<<(int)((n4 + 255) / 256), 256>>>(src, dst, n4);
}

extern "C" void kernel_launch(void* const* d_in, const int* in_sizes, int n_in,
                              void* d_out, int out_size) {
    const float* inputs = (const float*)d_in[0];
    const float* H0 = (const float*)d_in[2];
    const float* H1 = (const float*)d_in[3];
    const float* emb0 = (const float*)d_in[4];
    const float* emb1 = (const float*)d_in[5];
    const float* emb2 = (const float*)d_in[6];
    const float* fused = (const float*)d_in[7];
    const float *in_w[3], *in_b[3], *out_w[3], *out_b[3], *stack_w[3];
    for (int l = 0; l < 3; l++) {
        in_w[l] = (const float*)d_in[8 + 5 * l];
        in_b[l] = (const float*)d_in[9 + 5 * l];
        out_w[l] = (const float*)d_in[10 + 5 * l];
        out_b[l] = (const float*)d_in[11 + 5 * l];
        stack_w[l] = (const float*)d_in[12 + 5 * l];
    }
    float* outF = (float*)d_out;                // features (2048,512)
    float* outA = outF + (long)NL3 * D;         // attn_out (16,2048,512)

    float *E, *Q, *KV0, *KV1, *KV2, *OPRE, *OPRJ, *AGG, *R, *ADP0, *ATT;
    float *INPR, *INW, *OUTW, *FEATR;
    int *P1, *P2;
    SYM(E, g_E);   SYM(Q, g_Q);
    SYM(KV0, g_KV0); SYM(KV1, g_KV1); SYM(KV2, g_KV2);
    SYM(OPRE, g_OPRE); SYM(OPRJ, g_OPRJ);
    SYM(AGG, g_AGG);   SYM(R, g_R);
    SYM(ADP0, g_ADP0); SYM(ATT, g_ATT);
    SYM(P1, g_P1);     SYM(P2, g_P2);
    SYM(INPR, g_INPR); SYM(INW, g_INW);
    SYM(OUTW, g_OUTW); SYM(FEATR, g_FEATR);

    // parents + rounded operand staging
    extract_parents<<<(NL2 + NL3 + 255) / 256, 256>>>(H0, H1, P1, P2);
    launch_round(emb0, E, (long)64 * D);
    launch_round(emb1, E + 64 * D, (long)512 * D);
    launch_round(emb2, E + 576 * D, (long)2048 * D);
    launch_round(inputs, INPR, (long)BATCH * SEQ * D);
    for (int l = 0; l < 3; l++) {
        launch_round(in_w[l], INW + (long)l * 3 * D * D, (long)3 * D * D);
        launch_round(out_w[l], OUTW + (long)l * D * D, (long)D * D);
    }

    const int rowOff[3] = {0, 64, 576};
    const int mQ[3] = {64, 512, 2048};

    // Q projections (per level)
    for (int l = 0; l < 3; l++)
        launch_nt(Q + (long)rowOff[l] * D, E + (long)rowOff[l] * D,
                  INW + (long)l * 3 * D * D, in_b[l], mQ[l], D, D, 0, 0, 0, 1);
    // fused K|V projections: N=1024
    launch_nt(KV0, E, INW + 0L * 3 * D * D + (long)D * D, in_b[0] + D, 576, 1024, D, 0, 0, 0, 1);
    launch_nt(KV1, E, INW + 1L * 3 * D * D + (long)D * D, in_b[1] + D, 2624, 1024, D, 0, 0, 0, 1);
    launch_nt(KV2, E + 64 * D, INW + 2L * 3 * D * D + (long)D * D, in_b[2] + D, 2560, 1024, D, 0, 0, 0, 1);

    // agg: level 0 dense, levels 1/2 sibling groups (group_agg uses raw embs)
    launch_nt(ADP0, E, E, nullptr, 64, 64, D, 0, 0, 0, 1);
    row_softmax<<<64, 256>>>(ADP0, 64);
    launch_nn(AGG, ADP0, E, nullptr, 64, D, 64, 0, 0, 0, 1);
    group_agg<<<64, 256>>>(emb1, P1, NL2, AGG + 64 * D);
    group_agg<<<512, 256>>>(emb2, P2, NL3, AGG + 576 * D);

    // sparse MHA per level (fused KV, ld=1024)
    sparse_mha<<<64, 256>>>(Q, KV0, OPRE, nullptr, 0, P1, NL2, 64);
    sparse_mha<<<512, 256>>>(Q + 64 * D, KV1, OPRE + 64 * D, P1, 64, P2, NL3, 576);
    sparse_mha<<<2048, 256>>>(Q + 576 * D, KV2, OPRE + 576 * D, P2, 512, nullptr, 0, 0);

    // output projection
    for (int l = 0; l < 3; l++)
        launch_nt(OPRJ + (long)rowOff[l] * D, OPRE + (long)rowOff[l] * D,
                  OUTW + (long)l * D * D, out_b[l], mQ[l], D, D, 0, 0, 0, 1);

    // combine r = s0*agg + s1*h (raw emb values live in E rounded; use E) + s2*oproj
    for (int l = 0; l < 3; l++) {
        long n = (long)mQ[l] * D;
        combine_kernel<<<(int)((n + 255) / 256), 256>>>(
            AGG + (long)rowOff[l] * D, E + (long)rowOff[l] * D, OPRJ + (long)rowOff[l] * D,
            stack_w[l], R + (long)rowOff[l] * D, n);
    }

    // features -> d_out (+ rounded copy for the ATT GEMM)
    features_kernel<<<2048, 512>>>(R, P1, P2, fused, outF, FEATR);

    // final attention: logits, softmax, output
    launch_nt(ATT, FEATR, INPR, nullptr, NL3, SEQ, D, 0, (long)SEQ * D, (long)NL3 * SEQ, BATCH);
    row_softmax<<<BATCH * NL3, 256>>>(ATT, SEQ);
    launch_nn(outA, ATT, INPR, nullptr, NL3, D, SEQ, (long)NL3 * SEQ, (long)SEQ * D,
              (long)NL3 * D, BATCH);
}